// round 16
// baseline (speedup 1.0000x reference)
#include <cuda_runtime.h>
#include <cstdint>

#define NQ 2048
#define NT 5
#define NB 32
#define TPB 256
#define NPER 625              // 5^4 candidates per rank

static __device__ __forceinline__ unsigned long long umin64(unsigned long long a,
                                                            unsigned long long b) {
    return a < b ? a : b;
}
static __device__ __forceinline__ unsigned long long umax64(unsigned long long a,
                                                            unsigned long long b) {
    return a > b ? a : b;
}
#define CE(a, b) { unsigned long long _lo = umin64(a, b); b = umax64(a, b); a = _lo; }

// Merge sorted-ascending a[5] with DESCENDING brev[5]; keep 5 smallest sorted in a.
static __device__ __forceinline__ void merge_top5_rev(unsigned long long* a,
                                                      const unsigned long long* brev) {
    unsigned long long s0 = umin64(a[0], brev[0]);
    unsigned long long s1 = umin64(a[1], brev[1]);
    unsigned long long s2 = umin64(a[2], brev[2]);
    unsigned long long s3 = umin64(a[3], brev[3]);
    unsigned long long s4 = umin64(a[4], brev[4]);
    CE(s0, s1); CE(s3, s4); CE(s2, s4); CE(s2, s3); CE(s0, s3);
    CE(s0, s2); CE(s1, s4); CE(s1, s3); CE(s1, s2);
    a[0] = s0; a[1] = s1; a[2] = s2; a[3] = s3; a[4] = s4;
}

static __device__ __forceinline__ uint32_t smem_u32(const void* p) {
    uint32_t a;
    asm("{ .reg .u64 t; cvta.to.shared.u64 t, %1; cvt.u32.u64 %0, t; }"
        : "=r"(a) : "l"(p));
    return a;
}
static __device__ __forceinline__ void dsmem_st_u64(uint32_t local_addr, uint32_t rank,
                                                    unsigned long long v) {
    asm volatile(
        "{\n\t.reg .b32 r;\n\t"
        "mapa.shared::cluster.u32 r, %0, %1;\n\t"
        "st.shared::cluster.b64 [r], %2;\n\t}"
        :: "r"(local_addr), "r"(rank), "l"(v) : "memory");
}
static __device__ __forceinline__ void mbar_arrive_remote(uint32_t local_addr,
                                                          uint32_t rank) {
    asm volatile(
        "{\n\t.reg .b32 r;\n\t"
        "mapa.shared::cluster.u32 r, %0, %1;\n\t"
        "mbarrier.arrive.release.cluster.shared::cluster.b64 _, [r];\n\t}"
        :: "r"(local_addr), "r"(rank) : "memory");
}
static __device__ __forceinline__ void mbar_wait0(uint32_t addr) {
    asm volatile(
        "{\n\t.reg .pred P;\n\t"
        "W_%=:\n\t"
        "mbarrier.try_wait.parity.acquire.cluster.shared::cta.b64 P, [%0], 0;\n\t"
        "@!P bra W_%=;\n\t}"
        :: "r"(addr) : "memory");
}

__global__ __launch_bounds__(TPB, 1) __cluster_dims__(NT, 1, 1)
void hungarian_cluster_kernel(const float* __restrict__ pred_regs,  // [32,2048,3]
                              const float* __restrict__ tgt,        // [160,3]
                              float* __restrict__ out)              // [2,32,5] f32
{
    __shared__ unsigned long long sm_lists[8][NT];
    __shared__ unsigned long long keys_sm[NT][NT];   // [src_target][k], filled remotely
    __shared__ unsigned long long bests[NT][8];      // [rank][warp] partials (rank 0)
    __shared__ int   sel_idx[NT][NT];
    __shared__ float sel_val[NT][NT];
    __shared__ unsigned long long mbar_keys;         // count 5: one arrive per src CTA
    __shared__ unsigned long long mbar_best;         // count 32: 4 ranks x 8 warps

    const int b    = blockIdx.x / NT;
    const int t    = blockIdx.x % NT;                // == cluster rank
    const int tid  = threadIdx.x;
    const int w    = tid >> 5;
    const int lane = tid & 31;

    // ---- ISSUE all global loads FIRST ----
    const float t0f = __ldg(&tgt[b * NT * 3 + t * 3 + 0]);
    const float t1f = __ldg(&tgt[b * NT * 3 + t * 3 + 1]);
    const float t2f = __ldg(&tgt[b * NT * 3 + t * 3 + 2]);

    const float* pr = pred_regs + (size_t)b * NQ * 3;
    const int q0 = tid * 8;                          // q0*3 % 4 == 0
    const float4* p4 = (const float4*)(pr + (size_t)q0 * 3);
    float4 v0 = __ldg(&p4[0]);
    float4 v1 = __ldg(&p4[1]);
    float4 v2 = __ldg(&p4[2]);
    float4 v3 = __ldg(&p4[3]);
    float4 v4 = __ldg(&p4[4]);
    float4 v5 = __ldg(&p4[5]);

    // ---- init mbarriers + EARLY cluster arrive; wait deferred past scan ----
    if (tid == 0) {
        asm volatile("mbarrier.init.shared.b64 [%0], %1;"
                     :: "r"(smem_u32(&mbar_keys)), "r"(NT) : "memory");
        asm volatile("mbarrier.init.shared.b64 [%0], %1;"
                     :: "r"(smem_u32(&mbar_best)), "r"((NT - 1) * 8) : "memory");
    }
    asm volatile("barrier.cluster.arrive.aligned;" ::: "memory");

    // ---- unpack + scan (first consume of loads) ----
    float px[8], py[8], pz[8];
    px[0] = v0.x; py[0] = v0.y; pz[0] = v0.z;
    px[1] = v0.w; py[1] = v1.x; pz[1] = v1.y;
    px[2] = v1.z; py[2] = v1.w; pz[2] = v2.x;
    px[3] = v2.y; py[3] = v2.z; pz[3] = v2.w;
    px[4] = v3.x; py[4] = v3.y; pz[4] = v3.z;
    px[5] = v3.w; py[5] = v4.x; pz[5] = v4.y;
    px[6] = v4.z; py[6] = v4.w; pz[6] = v5.x;
    px[7] = v5.y; py[7] = v5.z; pz[7] = v5.w;

    // key = float_bits(cost)<<32 | q ; costs >= 1 > 0 so uint order == float
    // order; unique keys reproduce jax.lax.top_k's stable tie-break exactly.
    unsigned long long m[NT] = {~0ULL, ~0ULL, ~0ULL, ~0ULL, ~0ULL};
    #pragma unroll
    for (int e = 0; e < 8; e++) {
        float a0 = fabsf(__fsub_rn(px[e], t0f));
        float a1 = fabsf(__fsub_rn(py[e], t1f));
        float a2 = fabsf(__fsub_rn(pz[e], t2f));
        float c  = __fadd_rn(__fadd_rn(__fadd_rn(a0, a1), a2), 1.0f);
        unsigned long long key =
            ((unsigned long long)__float_as_uint(c) << 32) | (unsigned int)(q0 + e);
        if (key < m[4]) {
            m[4] = key;
            unsigned long long tmp;
            if (m[4] < m[3]) { tmp = m[3]; m[3] = m[4]; m[4] = tmp; }
            if (m[3] < m[2]) { tmp = m[2]; m[2] = m[3]; m[3] = tmp; }
            if (m[2] < m[1]) { tmp = m[1]; m[1] = m[2]; m[2] = tmp; }
            if (m[1] < m[0]) { tmp = m[0]; m[0] = m[1]; m[1] = tmp; }
        }
    }
    #pragma unroll
    for (int off = 16; off > 0; off >>= 1) {
        unsigned long long o[NT];
        #pragma unroll
        for (int k = 0; k < NT; k++)
            o[NT - 1 - k] = __shfl_xor_sync(0xffffffffu, m[k], off);
        merge_top5_rev(m, o);
    }
    if (lane == 0) {
        #pragma unroll
        for (int k = 0; k < NT; k++) sm_lists[w][k] = m[k];
    }
    __syncthreads();   // also makes local mbarrier init visible CTA-wide

    // ---- wait out remaining launch skew (usually already satisfied) ----
    asm volatile("barrier.cluster.wait.aligned;" ::: "memory");

    if (w == 0) {
        unsigned long long A[NT];
        #pragma unroll
        for (int k = 0; k < NT; k++)
            A[k] = (lane < 8) ? sm_lists[lane][k] : ~0ULL;
        #pragma unroll
        for (int off = 4; off > 0; off >>= 1) {
            unsigned long long o[NT];
            #pragma unroll
            for (int k = 0; k < NT; k++)
                o[NT - 1 - k] = __shfl_xor_sync(0xffffffffu, A[k], off);
            merge_top5_rev(A, o);
        }
        // ---- push my target's 5 keys into EVERY CTA's keys_sm[t][*] ----
        if (lane < NT) {
            #pragma unroll
            for (int k = 0; k < NT; k++)
                dsmem_st_u64(smem_u32(&keys_sm[t][k]), (uint32_t)lane, A[k]);
            mbar_arrive_remote(smem_u32(&mbar_keys), (uint32_t)lane);
        }
    }

    // ---- wait for all 25 keys; unpack (tid<25), then CTA sync ----
    if (tid < NT * NT) {
        mbar_wait0(smem_u32(&mbar_keys));
        unsigned long long v = keys_sm[tid / NT][tid % NT];
        sel_idx[tid / NT][tid % NT] = (int)(unsigned int)v;
        sel_val[tid / NT][tid % NT] = __uint_as_float((unsigned int)(v >> 32));
    }
    __syncthreads();

    // ---- this CTA enumerates d0 == t: 625 tuples (3 iters/thread) ----
    const int   e0 = sel_idx[0][t];
    const float c0 = sel_val[0][t];
    unsigned long long best = ~0ULL;
    for (int i = tid; i < NPER; i += TPB) {
        int r  = i;
        int d1 = r / 125;  r -= d1 * 125;
        int d2 = r / 25;   r -= d2 * 25;
        int d3 = r / 5;
        int d4 = r - d3 * 5;
        int e1 = sel_idx[1][d1], e2 = sel_idx[2][d2],
            e3 = sel_idx[3][d3], e4 = sel_idx[4][d4];
        bool valid = (e0 != e1) && (e0 != e2) && (e0 != e3) && (e0 != e4) &&
                     (e1 != e2) && (e1 != e3) && (e1 != e4) &&
                     (e2 != e3) && (e2 != e4) && (e3 != e4);
        if (valid) {
            float tot = __fadd_rn(
                            __fadd_rn(
                                __fadd_rn(
                                    __fadd_rn(c0, sel_val[1][d1]),
                                    sel_val[2][d2]),
                                sel_val[3][d3]),
                            sel_val[4][d4]);
            int n = t * NPER + i;    // global candidate index (tie-break)
            unsigned long long key =
                ((unsigned long long)__float_as_uint(tot) << 32) | (unsigned int)n;
            best = umin64(best, key);
        }
    }
    #pragma unroll
    for (int s = 16; s > 0; s >>= 1)
        best = umin64(best, __shfl_xor_sync(0xffffffffu, best, s));

    if (t != 0) {
        // ---- each warp's lane 0 pushes its partial straight to rank 0 ----
        if (lane == 0) {
            dsmem_st_u64(smem_u32(&bests[t][w]), 0u, best);
            mbar_arrive_remote(smem_u32(&mbar_best), 0u);
        }
        return;
    }

    // ---- rank 0: own partials to local smem, then warp 0 min over 40 ----
    if (lane == 0) bests[0][w] = best;
    __syncthreads();

    if (w == 0) {
        mbar_wait0(smem_u32(&mbar_best));   // 32 remote arrivals
        const unsigned long long* bf = &bests[0][0];   // 40 slots flat
        unsigned long long bb = bf[8 + lane];          // remote slots 8..39
        if (lane < 8) bb = umin64(bb, bf[lane]);       // own slots 0..7
        #pragma unroll
        for (int s = 16; s > 0; s >>= 1)
            bb = umin64(bb, __shfl_xor_sync(0xffffffffu, bb, s));

        if (lane == 0) {
            int n = (int)(unsigned int)bb;
            int d[NT];
            d[0] = n / 625; n %= 625;
            d[1] = n / 125; n %= 125;
            d[2] = n / 25;  n %= 25;
            d[3] = n / 5;
            d[4] = n % 5;
            int rows[NT], cols[NT];
            #pragma unroll
            for (int j = 0; j < NT; j++) { rows[j] = sel_idx[j][d[j]]; cols[j] = j; }
            #pragma unroll
            for (int i = 1; i < NT; i++) {     // stable insertion sort by rows
                int rv = rows[i], cv = cols[i], j = i - 1;
                while (j >= 0 && rows[j] > rv) {
                    rows[j + 1] = rows[j]; cols[j + 1] = cols[j]; j--;
                }
                rows[j + 1] = rv; cols[j + 1] = cv;
            }
            #pragma unroll
            for (int j = 0; j < NT; j++) {
                out[b * NT + j]           = (float)rows[j];   // rows [32,5]
                out[NB * NT + b * NT + j] = (float)cols[j];   // cols [32,5]
            }
        }
    }
}

extern "C" void kernel_launch(void* const* d_in, const int* in_sizes, int n_in,
                              void* d_out, int out_size) {
    // Bind by size (confirmed working): pred_regs = 196608 f32, tgt = 480 f32.
    int pr_i = -1, tg_i = -1, max_i = 0;
    for (int i = 0; i < n_in; i++) {
        if (in_sizes[i] == 196608 || in_sizes[i] == 786432) pr_i = i;
        if (in_sizes[i] == 480    || in_sizes[i] == 1920)   tg_i = i;
        if (in_sizes[i] > in_sizes[max_i]) max_i = i;
    }
    if (pr_i < 0) pr_i = max_i;
    if (tg_i < 0) tg_i = (n_in > 3) ? 3 : n_in - 1;

    const float* pred_regs = (const float*)d_in[pr_i];
    const float* tgt       = (const float*)d_in[tg_i];
    float* out = (float*)d_out;

    hungarian_cluster_kernel<<<NB * NT, TPB>>>(pred_regs, tgt, out);
}

// round 17
// speedup vs baseline: 1.0030x; 1.0030x over previous
#include <cuda_runtime.h>
#include <cstdint>

#define NQ 2048
#define NT 5
#define NB 32
#define TPB 256
#define NPER 625              // 5^4 candidates per rank

static __device__ __forceinline__ unsigned long long umin64(unsigned long long a,
                                                            unsigned long long b) {
    return a < b ? a : b;
}
static __device__ __forceinline__ unsigned long long umax64(unsigned long long a,
                                                            unsigned long long b) {
    return a > b ? a : b;
}
#define CE(a, b) { unsigned long long _lo = umin64(a, b); b = umax64(a, b); a = _lo; }

// Merge sorted-ascending a[5] with DESCENDING brev[5]; keep 5 smallest sorted in a.
static __device__ __forceinline__ void merge_top5_rev(unsigned long long* a,
                                                      const unsigned long long* brev) {
    unsigned long long s0 = umin64(a[0], brev[0]);
    unsigned long long s1 = umin64(a[1], brev[1]);
    unsigned long long s2 = umin64(a[2], brev[2]);
    unsigned long long s3 = umin64(a[3], brev[3]);
    unsigned long long s4 = umin64(a[4], brev[4]);
    CE(s0, s1); CE(s3, s4); CE(s2, s4); CE(s2, s3); CE(s0, s3);
    CE(s0, s2); CE(s1, s4); CE(s1, s3); CE(s1, s2);
    a[0] = s0; a[1] = s1; a[2] = s2; a[3] = s3; a[4] = s4;
}

static __device__ __forceinline__ uint32_t smem_u32(const void* p) {
    uint32_t a;
    asm("{ .reg .u64 t; cvta.to.shared.u64 t, %1; cvt.u32.u64 %0, t; }"
        : "=r"(a) : "l"(p));
    return a;
}
static __device__ __forceinline__ void dsmem_st_u64(uint32_t local_addr, uint32_t rank,
                                                    unsigned long long v) {
    asm volatile(
        "{\n\t.reg .b32 r;\n\t"
        "mapa.shared::cluster.u32 r, %0, %1;\n\t"
        "st.shared::cluster.b64 [r], %2;\n\t}"
        :: "r"(local_addr), "r"(rank), "l"(v) : "memory");
}
static __device__ __forceinline__ void mbar_arrive_remote(uint32_t local_addr,
                                                          uint32_t rank) {
    asm volatile(
        "{\n\t.reg .b32 r;\n\t"
        "mapa.shared::cluster.u32 r, %0, %1;\n\t"
        "mbarrier.arrive.release.cluster.shared::cluster.b64 _, [r];\n\t}"
        :: "r"(local_addr), "r"(rank) : "memory");
}
static __device__ __forceinline__ void mbar_wait0(uint32_t addr) {
    asm volatile(
        "{\n\t.reg .pred P;\n\t"
        "W_%=:\n\t"
        "mbarrier.try_wait.parity.acquire.cluster.shared::cta.b64 P, [%0], 0;\n\t"
        "@!P bra W_%=;\n\t}"
        :: "r"(addr) : "memory");
}

__global__ __launch_bounds__(TPB, 1) __cluster_dims__(NT, 1, 1)
void hungarian_cluster_kernel(const float* __restrict__ pred_regs,  // [32,2048,3]
                              const float* __restrict__ tgt,        // [160,3]
                              float* __restrict__ out)              // [2,32,5] f32
{
    __shared__ unsigned long long sm_lists[8][NT];
    __shared__ unsigned long long keys_sm[NT][NT];   // [src_target][k], filled remotely
    __shared__ unsigned long long bests[NT];         // partial argmins (used on rank 0)
    __shared__ int   sel_idx[NT][NT];
    __shared__ float sel_val[NT][NT];
    __shared__ unsigned long long red[8];
    __shared__ unsigned long long mbar_keys;         // count 5: one arrive per src CTA
    __shared__ unsigned long long mbar_best;         // count 4: arrivals from ranks 1..4

    const int b    = blockIdx.x / NT;
    const int t    = blockIdx.x % NT;                // == cluster rank
    const int tid  = threadIdx.x;
    const int w    = tid >> 5;
    const int lane = tid & 31;

    // ---- ISSUE all global loads FIRST ----
    const float t0f = __ldg(&tgt[b * NT * 3 + t * 3 + 0]);
    const float t1f = __ldg(&tgt[b * NT * 3 + t * 3 + 1]);
    const float t2f = __ldg(&tgt[b * NT * 3 + t * 3 + 2]);

    const float* pr = pred_regs + (size_t)b * NQ * 3;
    const int q0 = tid * 8;                          // q0*3 % 4 == 0
    const float4* p4 = (const float4*)(pr + (size_t)q0 * 3);
    float4 v0 = __ldg(&p4[0]);
    float4 v1 = __ldg(&p4[1]);
    float4 v2 = __ldg(&p4[2]);
    float4 v3 = __ldg(&p4[3]);
    float4 v4 = __ldg(&p4[4]);
    float4 v5 = __ldg(&p4[5]);

    // ---- init mbarriers + EARLY cluster arrive; wait deferred past scan ----
    if (tid == 0) {
        asm volatile("mbarrier.init.shared.b64 [%0], %1;"
                     :: "r"(smem_u32(&mbar_keys)), "r"(NT) : "memory");
        asm volatile("mbarrier.init.shared.b64 [%0], %1;"
                     :: "r"(smem_u32(&mbar_best)), "r"(NT - 1) : "memory");
    }
    asm volatile("barrier.cluster.arrive.aligned;" ::: "memory");

    // ---- unpack + build all 8 keys (pure ILP, no branches) ----
    float px[8], py[8], pz[8];
    px[0] = v0.x; py[0] = v0.y; pz[0] = v0.z;
    px[1] = v0.w; py[1] = v1.x; pz[1] = v1.y;
    px[2] = v1.z; py[2] = v1.w; pz[2] = v2.x;
    px[3] = v2.y; py[3] = v2.z; pz[3] = v2.w;
    px[4] = v3.x; py[4] = v3.y; pz[4] = v3.z;
    px[5] = v3.w; py[5] = v4.x; pz[5] = v4.y;
    px[6] = v4.z; py[6] = v4.w; pz[6] = v5.x;
    px[7] = v5.y; py[7] = v5.z; pz[7] = v5.w;

    // key = float_bits(cost)<<32 | q ; costs >= 1 > 0 so uint order == float
    // order; unique keys reproduce jax.lax.top_k's stable tie-break exactly.
    unsigned long long k[8];
    #pragma unroll
    for (int e = 0; e < 8; e++) {
        float a0 = fabsf(__fsub_rn(px[e], t0f));
        float a1 = fabsf(__fsub_rn(py[e], t1f));
        float a2 = fabsf(__fsub_rn(pz[e], t2f));
        float c  = __fadd_rn(__fadd_rn(__fadd_rn(a0, a1), a2), 1.0f);
        k[e] = ((unsigned long long)__float_as_uint(c) << 32) |
               (unsigned int)(q0 + e);
    }

    // ---- branchless Batcher odd-even mergesort on 8 keys (19 CE, depth 6) ----
    CE(k[0], k[1]); CE(k[2], k[3]); CE(k[4], k[5]); CE(k[6], k[7]);
    CE(k[0], k[2]); CE(k[1], k[3]); CE(k[4], k[6]); CE(k[5], k[7]);
    CE(k[1], k[2]); CE(k[5], k[6]);
    CE(k[0], k[4]); CE(k[1], k[5]); CE(k[2], k[6]); CE(k[3], k[7]);
    CE(k[2], k[4]); CE(k[3], k[5]);
    CE(k[1], k[2]); CE(k[3], k[4]); CE(k[5], k[6]);
    unsigned long long m[NT] = {k[0], k[1], k[2], k[3], k[4]};  // sorted top-5

    // ---- warp bitonic merge: 5 levels ----
    #pragma unroll
    for (int off = 16; off > 0; off >>= 1) {
        unsigned long long o[NT];
        #pragma unroll
        for (int kk = 0; kk < NT; kk++)
            o[NT - 1 - kk] = __shfl_xor_sync(0xffffffffu, m[kk], off);
        merge_top5_rev(m, o);
    }
    if (lane == 0) {
        #pragma unroll
        for (int kk = 0; kk < NT; kk++) sm_lists[w][kk] = m[kk];
    }
    __syncthreads();   // also makes local mbarrier init visible CTA-wide

    // ---- wait out remaining launch skew (usually already satisfied) ----
    asm volatile("barrier.cluster.wait.aligned;" ::: "memory");

    if (w == 0) {
        unsigned long long A[NT];
        #pragma unroll
        for (int kk = 0; kk < NT; kk++)
            A[kk] = (lane < 8) ? sm_lists[lane][kk] : ~0ULL;
        #pragma unroll
        for (int off = 4; off > 0; off >>= 1) {
            unsigned long long o[NT];
            #pragma unroll
            for (int kk = 0; kk < NT; kk++)
                o[NT - 1 - kk] = __shfl_xor_sync(0xffffffffu, A[kk], off);
            merge_top5_rev(A, o);
        }
        // ---- push my target's 5 keys into EVERY CTA's keys_sm[t][*] ----
        if (lane < NT) {
            #pragma unroll
            for (int kk = 0; kk < NT; kk++)
                dsmem_st_u64(smem_u32(&keys_sm[t][kk]), (uint32_t)lane, A[kk]);
            mbar_arrive_remote(smem_u32(&mbar_keys), (uint32_t)lane);
        }
    }

    // ---- wait for all 25 keys; unpack (tid<25), then CTA sync ----
    if (tid < NT * NT) {
        mbar_wait0(smem_u32(&mbar_keys));
        unsigned long long v = keys_sm[tid / NT][tid % NT];
        sel_idx[tid / NT][tid % NT] = (int)(unsigned int)v;
        sel_val[tid / NT][tid % NT] = __uint_as_float((unsigned int)(v >> 32));
    }
    __syncthreads();

    // ---- this CTA enumerates d0 == t: 625 tuples (3 iters/thread) ----
    const int   e0 = sel_idx[0][t];
    const float c0 = sel_val[0][t];
    unsigned long long best = ~0ULL;
    for (int i = tid; i < NPER; i += TPB) {
        int r  = i;
        int d1 = r / 125;  r -= d1 * 125;
        int d2 = r / 25;   r -= d2 * 25;
        int d3 = r / 5;
        int d4 = r - d3 * 5;
        int e1 = sel_idx[1][d1], e2 = sel_idx[2][d2],
            e3 = sel_idx[3][d3], e4 = sel_idx[4][d4];
        bool valid = (e0 != e1) && (e0 != e2) && (e0 != e3) && (e0 != e4) &&
                     (e1 != e2) && (e1 != e3) && (e1 != e4) &&
                     (e2 != e3) && (e2 != e4) && (e3 != e4);
        if (valid) {
            float tot = __fadd_rn(
                            __fadd_rn(
                                __fadd_rn(
                                    __fadd_rn(c0, sel_val[1][d1]),
                                    sel_val[2][d2]),
                                sel_val[3][d3]),
                            sel_val[4][d4]);
            int n = t * NPER + i;    // global candidate index (tie-break)
            unsigned long long key =
                ((unsigned long long)__float_as_uint(tot) << 32) | (unsigned int)n;
            best = umin64(best, key);
        }
    }
    #pragma unroll
    for (int s = 16; s > 0; s >>= 1)
        best = umin64(best, __shfl_xor_sync(0xffffffffu, best, s));
    if (lane == 0) red[w] = best;
    __syncthreads();

    unsigned long long bb = ~0ULL;
    if (w == 0) {
        bb = (lane < 8) ? red[lane] : ~0ULL;
        #pragma unroll
        for (int s = 4; s > 0; s >>= 1)
            bb = umin64(bb, __shfl_xor_sync(0xffffffffu, bb, s));
    }

    if (t != 0) {
        // push partial best to rank 0, arrive, and exit (no final barrier)
        if (tid == 0) {
            dsmem_st_u64(smem_u32(&bests[t]), 0u, bb);
            mbar_arrive_remote(smem_u32(&mbar_best), 0u);
        }
        return;
    }

    // ---- rank 0, thread 0: combine 5 partials, decode, sort, write ----
    if (tid == 0) {
        mbar_wait0(smem_u32(&mbar_best));
        #pragma unroll
        for (int i = 1; i < NT; i++) bb = umin64(bb, bests[i]);
        int n = (int)(unsigned int)bb;
        int d[NT];
        d[0] = n / 625; n %= 625;
        d[1] = n / 125; n %= 125;
        d[2] = n / 25;  n %= 25;
        d[3] = n / 5;
        d[4] = n % 5;
        int rows[NT], cols[NT];
        #pragma unroll
        for (int j = 0; j < NT; j++) { rows[j] = sel_idx[j][d[j]]; cols[j] = j; }
        #pragma unroll
        for (int i = 1; i < NT; i++) {     // stable insertion sort by rows
            int rv = rows[i], cv = cols[i], j = i - 1;
            while (j >= 0 && rows[j] > rv) {
                rows[j + 1] = rows[j]; cols[j + 1] = cols[j]; j--;
            }
            rows[j + 1] = rv; cols[j + 1] = cv;
        }
        #pragma unroll
        for (int j = 0; j < NT; j++) {
            out[b * NT + j]           = (float)rows[j];   // rows [32,5]
            out[NB * NT + b * NT + j] = (float)cols[j];   // cols [32,5]
        }
    }
}

extern "C" void kernel_launch(void* const* d_in, const int* in_sizes, int n_in,
                              void* d_out, int out_size) {
    // Bind by size (confirmed working): pred_regs = 196608 f32, tgt = 480 f32.
    int pr_i = -1, tg_i = -1, max_i = 0;
    for (int i = 0; i < n_in; i++) {
        if (in_sizes[i] == 196608 || in_sizes[i] == 786432) pr_i = i;
        if (in_sizes[i] == 480    || in_sizes[i] == 1920)   tg_i = i;
        if (in_sizes[i] > in_sizes[max_i]) max_i = i;
    }
    if (pr_i < 0) pr_i = max_i;
    if (tg_i < 0) tg_i = (n_in > 3) ? 3 : n_in - 1;

    const float* pred_regs = (const float*)d_in[pr_i];
    const float* tgt       = (const float*)d_in[tg_i];
    float* out = (float*)d_out;

    hungarian_cluster_kernel<<<NB * NT, TPB>>>(pred_regs, tgt, out);
}